// round 16
// baseline (speedup 1.0000x reference)
#include <cuda_runtime.h>
#include <cuda_fp16.h>
#include <cstdint>
#include <math.h>

#define B_   64
#define N_   512
#define D_   1024

#define CHB  16384            // one chunk: 128 rows x 128 B (swizzled, no pad)
#define RB_  256              // A row-blocks (128 rows each)
#define KT_  16               // K chunks of 64
#define NUNITS 512            // gemm units: (row-block, col-half)
#define LAG  16
// queue: [0,8) WhT, [8,72) tq, [72,840) groups of 3, [840,840+2*LAG) tail gemm
#define NTOT (72 + 768 + 2 * LAG)

// Scratch (device globals: no allocation allowed)
__device__ float g_tq[B_ * D_];
__device__ float g_part[2][B_ * N_];   // per-col-half partial logits
__device__ int   g_unit;               // work queue counter
__device__ int   g_flag[RB_];          // per-row-block conversion done
__device__ int   g_cnt_whT;            // 8 when WhT fully staged
__device__ int   g_cnt_tq;             // 64 when tq fully computed
__device__ __align__(128) unsigned char g_MhT[RB_ * KT_ * CHB];  // tiled fp16 A (64 MB)
__device__ __align__(128) unsigned char g_WhT[8 * KT_ * CHB];    // tiled fp16 Wh^T (2 MB)

// ---------------------------------------------------------------------------
// helpers
// ---------------------------------------------------------------------------
__device__ __forceinline__ uint32_t smem_u32(const void* p) {
    uint32_t a;
    asm("{ .reg .u64 t; cvta.to.shared.u64 t, %1; cvt.u32.u64 %0, t; }" : "=r"(a) : "l"(p));
    return a;
}
__device__ __forceinline__ float tanh_fast(float x) {
    float t;
    asm("tanh.approx.f32 %0, %1;" : "=f"(t) : "f"(x));
    return t;
}
__device__ __forceinline__ void ldsm4(uint32_t& r0, uint32_t& r1, uint32_t& r2, uint32_t& r3,
                                      uint32_t addr) {
    asm volatile("ldmatrix.sync.aligned.m8n8.x4.shared.b16 {%0,%1,%2,%3}, [%4];"
                 : "=r"(r0), "=r"(r1), "=r"(r2), "=r"(r3) : "r"(addr));
}
__device__ __forceinline__ void mma_f16(float* d, const uint32_t* a, const uint32_t* b) {
    asm volatile("mma.sync.aligned.m16n8k16.row.col.f32.f16.f16.f32 "
                 "{%0,%1,%2,%3}, {%4,%5,%6,%7}, {%8,%9}, {%0,%1,%2,%3};"
                 : "+f"(d[0]), "+f"(d[1]), "+f"(d[2]), "+f"(d[3])
                 : "r"(a[0]), "r"(a[1]), "r"(a[2]), "r"(a[3]), "r"(b[0]), "r"(b[1]));
}
__device__ __forceinline__ void mbar_init(uint32_t mb, uint32_t cnt) {
    asm volatile("mbarrier.init.shared.b64 [%0], %1;" :: "r"(mb), "r"(cnt) : "memory");
}
__device__ __forceinline__ void mbar_wait(uint32_t mb, uint32_t parity) {
    uint32_t done;
    asm volatile(
        "{\n\t.reg .pred p;\n\t"
        "mbarrier.try_wait.parity.acquire.cta.shared::cta.b64 p, [%1], %2;\n\t"
        "selp.b32 %0, 1, 0, p;\n\t}"
        : "=r"(done) : "r"(mb), "r"(parity) : "memory");
    if (!done) {
        asm volatile(
            "{\n\t.reg .pred P1;\n\t"
            "WL_%=:\n\t"
            "mbarrier.try_wait.parity.acquire.cta.shared::cta.b64 P1, [%0], %1, 0x989680;\n\t"
            "@P1 bra.uni WD_%=;\n\t"
            "bra.uni WL_%=;\n\t"
            "WD_%=:\n\t}"
            :: "r"(mb), "r"(parity) : "memory");
    }
}
__device__ __forceinline__ void tma_chunk(uint32_t sdst, const void* asrc,
                                          const void* bsrc, uint32_t mbar) {
    asm volatile("mbarrier.arrive.expect_tx.shared.b64 _, [%0], %1;"
                 :: "r"(mbar), "r"(2u * CHB) : "memory");
    asm volatile("cp.async.bulk.shared::cluster.global.mbarrier::complete_tx::bytes "
                 "[%0], [%1], %2, [%3];"
                 :: "r"(sdst), "l"(asrc), "r"((uint32_t)CHB), "r"(mbar) : "memory");
    asm volatile("cp.async.bulk.shared::cluster.global.mbarrier::complete_tx::bytes "
                 "[%0], [%1], %2, [%3];"
                 :: "r"(sdst + CHB), "l"(bsrc), "r"((uint32_t)CHB), "r"(mbar) : "memory");
}

// ---------------------------------------------------------------------------
// Kernel 0: reset queue + flags (each graph replay)
// ---------------------------------------------------------------------------
__global__ void init_kernel()
{
    const int t = threadIdx.x;
    if (t == 0) { g_unit = 0; g_cnt_whT = 0; g_cnt_tq = 0; }
    if (t < RB_) g_flag[t] = 0;
}

// ---------------------------------------------------------------------------
// Kernel 1 (fused everything): persistent 296 CTAs, one work queue.
//  u in [0,8):    WhT transpose unit (ct = u)          -> g_cnt_whT++
//  u in [8,72):   tq unit (t = u-8)                    -> g_cnt_tq++
//  u in [72,840): group j=u-72: j%3==0 -> conv rb=j/3  -> g_flag[rb]=1
//                 else gemm g = 2*(j/3 - LAG) + j%3-1  (skip if j/3 < LAG)
//  u in [840,NTOT): tail gemm g = 2*(256-LAG) + (u-840)
// ---------------------------------------------------------------------------
#define STG   (2 * CHB)           // 32768: A + B for one chunk
#define SRED  (3 * STG)           // 98304
#define SMB   (SRED + 512)        // 3 mbarriers
#define SMU   (SMB + 24)          // unit broadcast slot
#define SMTOT (SMU + 16)

__global__ __launch_bounds__(256, 2)
void fused_kernel(const float* __restrict__ M, const float* __restrict__ Wh,
                  const float* __restrict__ query, const float* __restrict__ Ws,
                  const float* __restrict__ v)
{
    extern __shared__ char smem[];
    const uint32_t sb = smem_u32(smem);
    float* red = (float*)(smem + SRED);
    float* sbuf = (float*)smem;             // reused by whT/tq units (stages idle)
    volatile int* su = (volatile int*)(smem + SMU);

    const int tid  = threadIdx.x;
    const int lane = tid & 31;
    const int wid  = tid >> 5;
    const int wm   = wid & 1;
    const int wn   = wid >> 1;
    const int gq   = lane >> 2;
    const int tg   = lane & 3;

    if (tid == 0) {
        mbar_init(sb + SMB + 0, 1);
        mbar_init(sb + SMB + 8, 1);
        mbar_init(sb + SMB + 16, 1);
        asm volatile("fence.proxy.async.shared::cta;" ::: "memory");
    }
    __syncthreads();

    // ldsm base offsets (swizzle: 16B unit ^= row&7)
    const uint32_t rmask  = (uint32_t)(lane & 7) << 4;
    const uint32_t a_base = (uint32_t)((wm * 64 + (lane & 15)) * 128);
    const uint32_t a_j    = (uint32_t)(lane >> 4);
    const uint32_t b_base = (uint32_t)(CHB + (wn * 32 + (lane & 7) + ((lane >> 4) & 1) * 8) * 128);
    const uint32_t b_j    = (uint32_t)((lane >> 3) & 1);

    uint32_t phases = 0;
    int s = 0;
    float acc[4][4][4];

    for (;;) {
        if (tid == 0) su[0] = atomicAdd(&g_unit, 1);
        __syncthreads();
        const int u = su[0];
        if (u >= NTOT) break;

        // ================= WhT transpose unit =================
        if (u < 8) {
            const int ct = u;
            float (*tr)[33] = (float(*)[33])sbuf;
            for (int p = 0; p < 128; p++) {
                const int kb = p >> 2, cb = ct * 4 + (p & 3);
                const int k0 = kb * 32, c0 = cb * 32;
                #pragma unroll
                for (int j = 0; j < 4; j++) {
                    int idx = tid + j * 256;
                    int i = idx >> 5, x = idx & 31;
                    tr[i][x] = Wh[(size_t)(k0 + i) * D_ + c0 + x];
                }
                __syncthreads();
                const int kt = kb >> 1;
                const int hb = (kb & 1) * 32;
                unsigned char* dst = g_WhT + (size_t)(ct * 16 + kt) * CHB;
                #pragma unroll
                for (int j = 0; j < 4; j++) {
                    int idx = tid + j * 256;
                    int i = idx >> 5, x = idx & 31;
                    int rloc = (c0 & 127) + i;
                    uint32_t off = (uint32_t)(rloc * 128 + (hb + x) * 2);
                    off ^= (uint32_t)(rloc & 7) << 4;
                    *(__half*)(dst + off) = __float2half_rn(tr[x][i]);
                }
                __syncthreads();
            }
            if (tid == 0) { __threadfence(); atomicAdd(&g_cnt_whT, 1); }
            continue;
        }

        // ================= tq unit =================
        if (u < 72) {
            const int t = u - 8;
            float (*Qs)[32]  = (float(*)[32])sbuf;
            float (*Wss)[64] = (float(*)[64])(sbuf + 512);
            const int a_local = tid & 63;
            const int br      = tid >> 6;
            const int a0      = (t & 15) * 64;
            const int b0      = (t >> 4) * 16;

            float tacc[4] = {0.f, 0.f, 0.f, 0.f};
            for (int k0 = 0; k0 < D_; k0 += 32) {
                #pragma unroll
                for (int i = 0; i < 2; i++) {
                    int idx = tid + i * 256;
                    Qs[idx >> 5][idx & 31] = query[(b0 + (idx >> 5)) * D_ + k0 + (idx & 31)];
                }
                #pragma unroll
                for (int i = 0; i < 8; i++) {
                    int idx = tid + i * 256;
                    Wss[idx >> 6][idx & 63] = Ws[(size_t)(k0 + (idx >> 6)) * D_ + a0 + (idx & 63)];
                }
                __syncthreads();
                #pragma unroll
                for (int kk = 0; kk < 32; kk++) {
                    float wv = Wss[kk][a_local];
                    #pragma unroll
                    for (int q = 0; q < 4; q++) tacc[q] += Qs[br + q * 4][kk] * wv;
                }
                __syncthreads();
            }
            #pragma unroll
            for (int q = 0; q < 4; q++)
                g_tq[(b0 + br + q * 4) * D_ + a0 + a_local] = tacc[q];
            if (tid == 0) { __threadfence(); atomicAdd(&g_cnt_tq, 1); }
            continue;
        }

        // ================= group dispatch =================
        int g;   // gemm unit id, or conv handled inline
        {
            const int j = u - 72;
            if (j < 768) {
                const int i = j / 3, r = j - i * 3;
                if (r == 0) {
                    // ----- conv unit: row-block i -> tiled+swizzled fp16 -----
                    const int rb = i;
                    unsigned char* dbase = g_MhT + (size_t)rb * (KT_ * CHB);
                    const float* srcb = M + ((size_t)rb << 17);   // rb*128*1024
                    for (int it = 0; it < 16; it++) {
                        #pragma unroll
                        for (int q = 0; q < 4; q++) {
                            const uint32_t idx = it * 1024 + q * 256 + tid;
                            const uint32_t c  = idx & 7;
                            const uint32_t r_ = (idx >> 3) & 127;
                            const uint32_t kt = idx >> 10;
                            const float4* src = (const float4*)(srcb + ((size_t)r_ << 10) + kt * 64 + c * 8);
                            float4 x = src[0];
                            float4 y = src[1];
                            __half2 h0 = __floats2half2_rn(x.x, x.y);
                            __half2 h1 = __floats2half2_rn(x.z, x.w);
                            __half2 h2 = __floats2half2_rn(y.x, y.y);
                            __half2 h3 = __floats2half2_rn(y.z, y.w);
                            uint4 o;
                            o.x = *(uint32_t*)&h0; o.y = *(uint32_t*)&h1;
                            o.z = *(uint32_t*)&h2; o.w = *(uint32_t*)&h3;
                            const uint32_t cs = c ^ (r_ & 7);
                            *(uint4*)(dbase + (size_t)kt * CHB + r_ * 128 + cs * 16) = o;
                        }
                    }
                    __syncthreads();
                    if (tid == 0) { __threadfence(); atomicExch(&g_flag[rb], 1); }
                    continue;
                }
                if (i < LAG) continue;            // invalid early gemm slot
                g = 2 * (i - LAG) + (r - 1);
            } else {
                g = 2 * (RB_ - LAG) + (j - 768);  // tail gemm units
            }
        }

        // ================= gemm unit =================
        const int rb   = g >> 1;
        const int h    = g & 1;
        const int row0 = rb * 128;
        const int b    = rb >> 2;
        const unsigned char* Abase = g_MhT + (size_t)rb * (KT_ * CHB);
        const unsigned char* Bbase = g_WhT + (size_t)(h * 4 * 16) * CHB;

        // wait for producers (single thread polls; deps are earlier queue units)
        if (tid == 0) {
            while (((volatile int*)g_flag)[rb] == 0) { }
            while (*(volatile int*)&g_cnt_whT < 8) { }
            while (*(volatile int*)&g_cnt_tq < 64) { }
        }
        __syncthreads();

        if (tid < 128) red[tid] = 0.f;

        float part[8];
        #pragma unroll
        for (int i = 0; i < 8; i++) part[i] = 0.f;

        if (tid == 0) {
            int s1 = (s + 1 == 3) ? 0 : s + 1;
            tma_chunk(sb + s * STG,  Abase + 0 * CHB, Bbase + 0 * CHB, sb + SMB + s * 8);
            tma_chunk(sb + s1 * STG, Abase + 1 * CHB, Bbase + 1 * CHB, sb + SMB + s1 * 8);
        }

        for (int ch = 0; ch < 64; ch++) {
            const int kt = ch & 15;
            if (kt == 0) {
                #pragma unroll
                for (int mi = 0; mi < 4; mi++)
                    #pragma unroll
                    for (int ni = 0; ni < 4; ni++)
                        #pragma unroll
                        for (int q = 0; q < 4; q++) acc[mi][ni][q] = 0.f;
            }

            if (wid == 0) mbar_wait(sb + SMB + s * 8, (phases >> s) & 1);
            phases ^= (1u << s);
            __syncthreads();

            if (tid == 0 && ch + 2 < 64) {
                const int ch2 = ch + 2;
                int s2 = s + 2; if (s2 >= 3) s2 -= 3;
                tma_chunk(sb + s2 * STG,
                          Abase + (size_t)(ch2 & 15) * CHB,
                          Bbase + (size_t)(((ch2 >> 4) * 16) + (ch2 & 15)) * CHB,
                          sb + SMB + s2 * 8);
            }

            const uint32_t sA = sb + s * STG;
            #pragma unroll
            for (int ks = 0; ks < 4; ks++) {
                const uint32_t au = ((uint32_t)(ks * 2 + a_j) << 4) ^ rmask;
                const uint32_t bu = ((uint32_t)(ks * 2 + b_j) << 4) ^ rmask;
                uint32_t a[4][4];
                #pragma unroll
                for (int mi = 0; mi < 4; mi++)
                    ldsm4(a[mi][0], a[mi][1], a[mi][2], a[mi][3],
                          sA + a_base + mi * 2048 + au);
                uint32_t bf[4][2];
                #pragma unroll
                for (int np = 0; np < 2; np++) {
                    uint32_t r0, r1, r2, r3;
                    ldsm4(r0, r1, r2, r3, sA + b_base + np * 2048 + bu);
                    bf[np * 2 + 0][0] = r0; bf[np * 2 + 0][1] = r1;
                    bf[np * 2 + 1][0] = r2; bf[np * 2 + 1][1] = r3;
                }
                #pragma unroll
                for (int mi = 0; mi < 4; mi++)
                    #pragma unroll
                    for (int ni = 0; ni < 4; ni++)
                        mma_f16(acc[mi][ni], a[mi], bf[ni]);
            }

            if (kt == 15) {
                const int c0 = (h * 4 + (ch >> 4)) << 7;
                #pragma unroll
                for (int ni = 0; ni < 4; ni++) {
                    const int cg = c0 + wn * 32 + ni * 8 + tg * 2;
                    const float tq0 = __ldg(&g_tq[b * D_ + cg]);
                    const float tq1 = __ldg(&g_tq[b * D_ + cg + 1]);
                    const float v0  = __ldg(&v[cg]);
                    const float v1  = __ldg(&v[cg + 1]);
                    #pragma unroll
                    for (int mi = 0; mi < 4; mi++) {
                        part[2 * mi]     += tanh_fast(acc[mi][ni][0] + tq0) * v0
                                          + tanh_fast(acc[mi][ni][1] + tq1) * v1;
                        part[2 * mi + 1] += tanh_fast(acc[mi][ni][2] + tq0) * v0
                                          + tanh_fast(acc[mi][ni][3] + tq1) * v1;
                    }
                }
            }
            if (++s == 3) s = 0;
        }

        #pragma unroll
        for (int i = 0; i < 8; i++) {
            float p = part[i];
            p += __shfl_xor_sync(0xFFFFFFFFu, p, 1);
            p += __shfl_xor_sync(0xFFFFFFFFu, p, 2);
            if (tg == 0) {
                int row = wm * 64 + (i >> 1) * 16 + (i & 1) * 8 + gq;
                atomicAdd(&red[row], p);
            }
        }
        __syncthreads();
        if (tid < 128) g_part[h][row0 + tid] = red[tid];
    }
}

// ---------------------------------------------------------------------------
// Kernel 2: fused masked softmax + context (reads tiled+swizzled fp16 M)
// ---------------------------------------------------------------------------
__global__ __launch_bounds__(256, 4)
void ctx_softmax(const int* __restrict__ mask, float* __restrict__ out)
{
    __shared__ float ws[N_];
    __shared__ float sred[256];
    const int b = blockIdx.y;
    const int t = threadIdx.x;

    const int   mk0 = mask[b * N_ + t];
    const int   mk1 = mask[b * N_ + t + 256];
    const float l0  = g_part[0][b * N_ + t] + g_part[1][b * N_ + t];
    const float l1  = g_part[0][b * N_ + t + 256] + g_part[1][b * N_ + t + 256];

    int any = __syncthreads_or(mk0 | mk1);
    if (!any) {
        float2 z = {0.f, 0.f};
        ((float2*)(out + b * D_))[blockIdx.x * 256 + t] = z;
        return;
    }
    float x0 = mk0 ? l0 : -1e30f;
    float x1 = mk1 ? l1 : -1e30f;

    sred[t] = fmaxf(x0, x1);
    __syncthreads();
    #pragma unroll
    for (int st = 128; st > 0; st >>= 1) {
        if (t < st) sred[t] = fmaxf(sred[t], sred[t + st]);
        __syncthreads();
    }
    const float mx = sred[0];
    __syncthreads();
    const float e0 = expf(x0 - mx);
    const float e1 = expf(x1 - mx);
    sred[t] = e0 + e1;
    __syncthreads();
    #pragma unroll
    for (int st = 128; st > 0; st >>= 1) {
        if (t < st) sred[t] += sred[t + st];
        __syncthreads();
    }
    const float inv = 1.f / sred[0];
    ws[t]       = e0 * inv;
    ws[t + 256] = e1 * inv;
    __syncthreads();

    const int d      = 2 * (blockIdx.x * 256 + t);
    const int kt     = d >> 6;
    const uint32_t off_d = (uint32_t)(((d & 63) >> 3) * 16 + (d & 7) * 2);

    float2 a0 = {0.f, 0.f}, a1 = {0.f, 0.f}, a2 = {0.f, 0.f}, a3 = {0.f, 0.f};
    #pragma unroll
    for (int nb = 0; nb < 4; nb++) {
        const unsigned char* base = g_MhT + (size_t)((b * 4 + nb) * 16 + kt) * CHB;
        const float* w = ws + nb * 128;
        #pragma unroll 4
        for (int r = 0; r < 128; r += 4) {
            float2 m0 = __half22float2(*(const __half2*)(base + (r + 0) * 128 + (off_d ^ (((r + 0) & 7) << 4))));
            float2 m1 = __half22float2(*(const __half2*)(base + (r + 1) * 128 + (off_d ^ (((r + 1) & 7) << 4))));
            float2 m2 = __half22float2(*(const __half2*)(base + (r + 2) * 128 + (off_d ^ (((r + 2) & 7) << 4))));
            float2 m3 = __half22float2(*(const __half2*)(base + (r + 3) * 128 + (off_d ^ (((r + 3) & 7) << 4))));
            a0.x += w[r + 0] * m0.x; a0.y += w[r + 0] * m0.y;
            a1.x += w[r + 1] * m1.x; a1.y += w[r + 1] * m1.y;
            a2.x += w[r + 2] * m2.x; a2.y += w[r + 2] * m2.y;
            a3.x += w[r + 3] * m3.x; a3.y += w[r + 3] * m3.y;
        }
    }
    float2 rr;
    rr.x = (a0.x + a1.x) + (a2.x + a3.x);
    rr.y = (a0.y + a1.y) + (a2.y + a3.y);
    ((float2*)(out + b * D_))[blockIdx.x * 256 + t] = rr;
}

// ---------------------------------------------------------------------------
extern "C" void kernel_launch(void* const* d_in, const int* in_sizes, int n_in,
                              void* d_out, int out_size)
{
    const float* M     = (const float*)d_in[0];  // (64, 512, 1024)
    const int*   mask  = (const int*)  d_in[1];  // (64, 512)
    const float* query = (const float*)d_in[2];  // (64, 1024)
    const float* Wh    = (const float*)d_in[3];  // (1024, 1024)
    const float* Ws    = (const float*)d_in[4];  // (1024, 1024)
    const float* v     = (const float*)d_in[5];  // (1024, 1)
    float* out = (float*)d_out;                  // (64, 1024)

    cudaFuncSetAttribute(fused_kernel, cudaFuncAttributeMaxDynamicSharedMemorySize, SMTOT);

    init_kernel<<<1, 256>>>();
    fused_kernel<<<296, 256, SMTOT>>>(M, Wh, query, Ws, v);
    ctx_softmax<<<dim3(2, B_), 256>>>(mask, out);
}

// round 17
// speedup vs baseline: 1.5220x; 1.5220x over previous
#include <cuda_runtime.h>
#include <cuda_fp16.h>
#include <cstdint>
#include <math.h>

#define B_   64
#define N_   512
#define D_   1024

#define CHB  16384            // one chunk: 128 rows x 128 B (swizzled, no pad)
#define RB_  256              // A row-blocks (128 rows each)
#define KT_  16               // K chunks of 64
#define NUNITS 2048           // work units: (row-block, c-tile) 128x128

// Scratch (device globals: no allocation allowed)
__device__ float g_tq[B_ * D_];
__device__ float g_part8[8][B_ * N_];  // per-c-tile partial logits (1 MB)
__device__ int   g_unit;               // work queue counter (reset in prep)
__device__ __align__(128) unsigned char g_MhT[RB_ * KT_ * CHB];  // tiled fp16 A (64 MB)
__device__ __align__(128) unsigned char g_WhT[8 * KT_ * CHB];    // tiled fp16 Wh^T (2 MB)

// ---------------------------------------------------------------------------
// helpers
// ---------------------------------------------------------------------------
__device__ __forceinline__ uint32_t smem_u32(const void* p) {
    uint32_t a;
    asm("{ .reg .u64 t; cvta.to.shared.u64 t, %1; cvt.u32.u64 %0, t; }" : "=r"(a) : "l"(p));
    return a;
}
__device__ __forceinline__ float tanh_fast(float x) {
    float t;
    asm("tanh.approx.f32 %0, %1;" : "=f"(t) : "f"(x));
    return t;
}
__device__ __forceinline__ void ldsm4(uint32_t& r0, uint32_t& r1, uint32_t& r2, uint32_t& r3,
                                      uint32_t addr) {
    asm volatile("ldmatrix.sync.aligned.m8n8.x4.shared.b16 {%0,%1,%2,%3}, [%4];"
                 : "=r"(r0), "=r"(r1), "=r"(r2), "=r"(r3) : "r"(addr));
}
__device__ __forceinline__ void mma_f16(float* d, const uint32_t* a, const uint32_t* b) {
    asm volatile("mma.sync.aligned.m16n8k16.row.col.f32.f16.f16.f32 "
                 "{%0,%1,%2,%3}, {%4,%5,%6,%7}, {%8,%9}, {%0,%1,%2,%3};"
                 : "+f"(d[0]), "+f"(d[1]), "+f"(d[2]), "+f"(d[3])
                 : "r"(a[0]), "r"(a[1]), "r"(a[2]), "r"(a[3]), "r"(b[0]), "r"(b[1]));
}
__device__ __forceinline__ void mbar_init(uint32_t mb, uint32_t cnt) {
    asm volatile("mbarrier.init.shared.b64 [%0], %1;" :: "r"(mb), "r"(cnt) : "memory");
}
__device__ __forceinline__ void mbar_wait(uint32_t mb, uint32_t parity) {
    uint32_t done;
    asm volatile(
        "{\n\t.reg .pred p;\n\t"
        "mbarrier.try_wait.parity.acquire.cta.shared::cta.b64 p, [%1], %2;\n\t"
        "selp.b32 %0, 1, 0, p;\n\t}"
        : "=r"(done) : "r"(mb), "r"(parity) : "memory");
    if (!done) {
        asm volatile(
            "{\n\t.reg .pred P1;\n\t"
            "WL_%=:\n\t"
            "mbarrier.try_wait.parity.acquire.cta.shared::cta.b64 P1, [%0], %1, 0x989680;\n\t"
            "@P1 bra.uni WD_%=;\n\t"
            "bra.uni WL_%=;\n\t"
            "WD_%=:\n\t}"
            :: "r"(mb), "r"(parity) : "memory");
    }
}
// issue one chunk: A (16384 B) + B (16384 B) into stage, tracked by one mbarrier
__device__ __forceinline__ void tma_chunk(uint32_t sdst, const void* asrc,
                                          const void* bsrc, uint32_t mbar) {
    asm volatile("mbarrier.arrive.expect_tx.shared.b64 _, [%0], %1;"
                 :: "r"(mbar), "r"(2u * CHB) : "memory");
    asm volatile("cp.async.bulk.shared::cluster.global.mbarrier::complete_tx::bytes "
                 "[%0], [%1], %2, [%3];"
                 :: "r"(sdst), "l"(asrc), "r"((uint32_t)CHB), "r"(mbar) : "memory");
    asm volatile("cp.async.bulk.shared::cluster.global.mbarrier::complete_tx::bytes "
                 "[%0], [%1], %2, [%3];"
                 :: "r"(sdst + CHB), "l"(bsrc), "r"((uint32_t)CHB), "r"(mbar) : "memory");
}

// ---------------------------------------------------------------------------
// Kernel 1 (fused prep): tq = query@Ws (blocks 0..63), WhT tiled+swizzled fp16
// (next 1024 blocks), M -> tiled+swizzled fp16 (8192 blocks, 2 units/thread)
// Swizzle: 16B unit u within a 128B row r sits at physical unit (u ^ (r&7)).
// ---------------------------------------------------------------------------
#define TQ_BLKS   64
#define TRAN_BLKS 1024
#define CONV_BLKS 8192
#define HALF_UNITS 2097152u      // 4,194,304 16B-units / 2

__global__ __launch_bounds__(256)
void prep_kernel(const float* __restrict__ M, const float* __restrict__ Wh,
                 const float* __restrict__ query, const float* __restrict__ Ws)
{
    __shared__ float sbuf[2624];
    const int bid = blockIdx.x;
    const int tid = threadIdx.x;

    if (bid < TQ_BLKS) {
        if (bid == 0 && tid == 0) g_unit = 0;    // reset work queue each launch
        // ----- tq = query @ Ws -----
        float (*Qs)[32]  = (float(*)[32])sbuf;          // 16 x 32
        float (*Wss)[64] = (float(*)[64])(sbuf + 512);  // 32 x 64
        const int a_local = tid & 63;
        const int br      = tid >> 6;
        const int a0      = (bid & 15) * 64;
        const int b0      = (bid >> 4) * 16;

        float acc[4] = {0.f, 0.f, 0.f, 0.f};
        for (int k0 = 0; k0 < D_; k0 += 32) {
            #pragma unroll
            for (int i = 0; i < 2; i++) {
                int idx = tid + i * 256;
                Qs[idx >> 5][idx & 31] = query[(b0 + (idx >> 5)) * D_ + k0 + (idx & 31)];
            }
            #pragma unroll
            for (int i = 0; i < 8; i++) {
                int idx = tid + i * 256;
                Wss[idx >> 6][idx & 63] = Ws[(size_t)(k0 + (idx >> 6)) * D_ + a0 + (idx & 63)];
            }
            __syncthreads();
            #pragma unroll
            for (int kk = 0; kk < 32; kk++) {
                float wv = Wss[kk][a_local];
                #pragma unroll
                for (int q = 0; q < 4; q++) acc[q] += Qs[br + q * 4][kk] * wv;
            }
            __syncthreads();
        }
        #pragma unroll
        for (int q = 0; q < 4; q++)
            g_tq[(b0 + br + q * 4) * D_ + a0 + a_local] = acc[q];
    } else if (bid < TQ_BLKS + TRAN_BLKS) {
        // ----- WhT tiled+swizzled: chunk (ct,kt), row = out-col c -----
        const int t  = bid - TQ_BLKS;
        const int kb = t >> 5, cb = t & 31;
        const int k0 = kb * 32, c0 = cb * 32;
        float (*tr)[33] = (float(*)[33])sbuf;
        #pragma unroll
        for (int j = 0; j < 4; j++) {
            int idx = tid + j * 256;
            int i = idx >> 5, x = idx & 31;
            tr[i][x] = Wh[(size_t)(k0 + i) * D_ + c0 + x];
        }
        __syncthreads();
        const int ct = c0 >> 7;
        const int kt = kb >> 1;
        const int hb = (kb & 1) * 32;
        unsigned char* dst = g_WhT + (size_t)(ct * 16 + kt) * CHB;
        #pragma unroll
        for (int j = 0; j < 4; j++) {
            int idx = tid + j * 256;
            int i = idx >> 5, x = idx & 31;
            int rloc = (c0 & 127) + i;
            uint32_t off = (uint32_t)(rloc * 128 + (hb + x) * 2);
            off ^= (uint32_t)(rloc & 7) << 4;
            *(__half*)(dst + off) = __float2half_rn(tr[x][i]);
        }
    } else {
        // ----- M -> tiled+swizzled fp16: TWO 16B units per thread -----
        const uint32_t idx = (uint32_t)(bid - TQ_BLKS - TRAN_BLKS) * 256 + tid;
        #pragma unroll
        for (int half = 0; half < 2; half++) {
            const uint32_t u  = idx + half * HALF_UNITS;
            const uint32_t c  = u & 7;
            const uint32_t r  = (u >> 3) & 127;
            const uint32_t kt = (u >> 10) & 15;
            const uint32_t rb = u >> 14;
            const float4* src = (const float4*)(M + ((size_t)(rb * 128 + r) << 10) + kt * 64 + c * 8);
            float4 x = src[0];
            float4 y = src[1];
            __half2 h0 = __floats2half2_rn(x.x, x.y);
            __half2 h1 = __floats2half2_rn(x.z, x.w);
            __half2 h2 = __floats2half2_rn(y.x, y.y);
            __half2 h3 = __floats2half2_rn(y.z, y.w);
            uint4 o;
            o.x = *(uint32_t*)&h0; o.y = *(uint32_t*)&h1;
            o.z = *(uint32_t*)&h2; o.w = *(uint32_t*)&h3;
            const uint32_t cs = c ^ (r & 7);
            *(uint4*)(g_MhT + (size_t)(rb * 16 + kt) * CHB + r * 128 + cs * 16) = o;
        }
    }
}

// ---------------------------------------------------------------------------
// Kernel 2 (dominant): fp16 m16n8k16 mma GEMM + fused tanh·v epilogue
// Persistent 296 CTAs (2/SM); 2048 fine units (128 rows x ONE 128-col c-tile,
// 16 K-chunks). 3-stage TMA ring rolls ACROSS units: at kt=14 the issuer
// grabs the next unit and pre-issues its chunks 0,1 — no drain bubble.
// ---------------------------------------------------------------------------
#define STG   (2 * CHB)           // 32768: A + B for one chunk
#define SRED  (3 * STG)           // 98304
#define SMB   (SRED + 512)        // 3 mbarriers
#define SMU   (SMB + 24)          // unit broadcast slots (2)
#define SMTOT (SMU + 16)

__global__ __launch_bounds__(256, 2)
void logits_mma(const float* __restrict__ v)
{
    extern __shared__ char smem[];
    const uint32_t sb = smem_u32(smem);
    float* red = (float*)(smem + SRED);
    volatile int* su = (volatile int*)(smem + SMU);

    const int tid  = threadIdx.x;
    const int lane = tid & 31;
    const int wid  = tid >> 5;
    const int wm   = wid & 1;          // m block (2 x 64 rows)
    const int wn   = wid >> 1;         // n block (4 x 32 cols)
    const int gq   = lane >> 2;
    const int tg   = lane & 3;

    if (tid == 0) {
        mbar_init(sb + SMB + 0, 1);
        mbar_init(sb + SMB + 8, 1);
        mbar_init(sb + SMB + 16, 1);
        asm volatile("fence.proxy.async.shared::cta;" ::: "memory");
    }
    __syncthreads();

    // ldsm base offsets (swizzle: 16B unit ^= row&7; row deltas ≡0 mod 8)
    const uint32_t rmask  = (uint32_t)(lane & 7) << 4;
    const uint32_t a_base = (uint32_t)((wm * 64 + (lane & 15)) * 128);
    const uint32_t a_j    = (uint32_t)(lane >> 4);
    const uint32_t b_base = (uint32_t)(CHB + (wn * 32 + (lane & 7) + ((lane >> 4) & 1) * 8) * 128);
    const uint32_t b_j    = (uint32_t)((lane >> 3) & 1);

    uint32_t phases = 0;
    int s = 0;
    float acc[4][4][4];

    // ---- initial unit grab + prologue ----
    if (tid == 0) su[0] = atomicAdd(&g_unit, 1);
    __syncthreads();
    int u = su[0];
    if (u < NUNITS) {
        int rb = u >> 3, ct = u & 7;
        const unsigned char* Abase = g_MhT + (size_t)rb * (KT_ * CHB);
        const unsigned char* Bbase = g_WhT + (size_t)(ct * 16) * CHB;
        if (tid == 0) {
            tma_chunk(sb + 0 * STG, Abase + 0 * CHB, Bbase + 0 * CHB, sb + SMB + 0);
            tma_chunk(sb + 1 * STG, Abase + 1 * CHB, Bbase + 1 * CHB, sb + SMB + 8);
        }
        if (tid < 128) red[tid] = 0.f;

        while (true) {
            const int row0 = rb * 128;
            const int b    = rb >> 2;

            #pragma unroll
            for (int mi = 0; mi < 4; mi++)
                #pragma unroll
                for (int ni = 0; ni < 4; ni++)
                    #pragma unroll
                    for (int q = 0; q < 4; q++) acc[mi][ni][q] = 0.f;

            float part[8];
            #pragma unroll
            for (int i = 0; i < 8; i++) part[i] = 0.f;

            int nu = 0x7FFFFFFF;   // tid0-local next unit

            for (int kt = 0; kt < KT_; kt++) {
                if (wid == 0) mbar_wait(sb + SMB + s * 8, (phases >> s) & 1);
                phases ^= (1u << s);
                __syncthreads();             // visibility + stage s2 drained

                // lookahead issue: chunk kt+2 (may belong to the next unit)
                if (tid == 0) {
                    int s2 = s + 2; if (s2 >= 3) s2 -= 3;
                    const int la = kt + 2;
                    if (la < KT_) {
                        tma_chunk(sb + s2 * STG,
                                  Abase + (size_t)la * CHB,
                                  Bbase + (size_t)la * CHB,
                                  sb + SMB + s2 * 8);
                    } else {
                        if (la == KT_) { nu = atomicAdd(&g_unit, 1); su[1] = nu; }
                        if (nu < NUNITS) {
                            const int nrb = nu >> 3, nct = nu & 7;
                            const unsigned char* nA = g_MhT + (size_t)nrb * (KT_ * CHB);
                            const unsigned char* nB = g_WhT + (size_t)(nct * 16) * CHB;
                            const int lkt = la - KT_;
                            tma_chunk(sb + s2 * STG,
                                      nA + (size_t)lkt * CHB,
                                      nB + (size_t)lkt * CHB,
                                      sb + SMB + s2 * 8);
                        }
                    }
                }

                const uint32_t sA = sb + s * STG;
                #pragma unroll
                for (int ks = 0; ks < 4; ks++) {
                    const uint32_t au = ((uint32_t)(ks * 2 + a_j) << 4) ^ rmask;
                    const uint32_t bu = ((uint32_t)(ks * 2 + b_j) << 4) ^ rmask;
                    uint32_t a[4][4];
                    #pragma unroll
                    for (int mi = 0; mi < 4; mi++)
                        ldsm4(a[mi][0], a[mi][1], a[mi][2], a[mi][3],
                              sA + a_base + mi * 2048 + au);
                    uint32_t bf[4][2];
                    #pragma unroll
                    for (int np = 0; np < 2; np++) {
                        uint32_t r0, r1, r2, r3;
                        ldsm4(r0, r1, r2, r3, sA + b_base + np * 2048 + bu);
                        bf[np * 2 + 0][0] = r0; bf[np * 2 + 0][1] = r1;
                        bf[np * 2 + 1][0] = r2; bf[np * 2 + 1][1] = r3;
                    }
                    #pragma unroll
                    for (int mi = 0; mi < 4; mi++)
                        #pragma unroll
                        for (int ni = 0; ni < 4; ni++)
                            mma_f16(acc[mi][ni], a[mi], bf[ni]);
                }
                if (++s == 3) s = 0;
            }

            // epilogue: tanh + dot with v over this unit's 128 cols
            {
                const int c0 = ct << 7;
                #pragma unroll
                for (int ni = 0; ni < 4; ni++) {
                    const int cg = c0 + wn * 32 + ni * 8 + tg * 2;
                    const float tq0 = __ldg(&g_tq[b * D_ + cg]);
                    const float tq1 = __ldg(&g_tq[b * D_ + cg + 1]);
                    const float v0  = __ldg(&v[cg]);
                    const float v1  = __ldg(&v[cg + 1]);
                    #pragma unroll
                    for (int mi = 0; mi < 4; mi++) {
                        part[2 * mi]     += tanh_fast(acc[mi][ni][0] + tq0) * v0
                                          + tanh_fast(acc[mi][ni][1] + tq1) * v1;
                        part[2 * mi + 1] += tanh_fast(acc[mi][ni][2] + tq0) * v0
                                          + tanh_fast(acc[mi][ni][3] + tq1) * v1;
                    }
                }
            }
            #pragma unroll
            for (int i = 0; i < 8; i++) {
                float p = part[i];
                p += __shfl_xor_sync(0xFFFFFFFFu, p, 1);
                p += __shfl_xor_sync(0xFFFFFFFFu, p, 2);
                if (tg == 0) {
                    int row = wm * 64 + (i >> 1) * 16 + (i & 1) * 8 + gq;
                    atomicAdd(&red[row], p);
                }
            }
            __syncthreads();
            if (tid < 128) g_part8[ct][row0 + tid] = red[tid];
            __syncthreads();                  // partial stored; su[1] visible

            u = su[1];
            if (u >= NUNITS) break;
            rb = u >> 3; ct = u & 7;
            Abase = g_MhT + (size_t)rb * (KT_ * CHB);
            Bbase = g_WhT + (size_t)(ct * 16) * CHB;
            if (tid < 128) red[tid] = 0.f;    // ordered by chunk-0 sync
        }
    }
}

// ---------------------------------------------------------------------------
// Kernel 3: fused masked softmax + context (reads tiled+swizzled fp16 M)
// ---------------------------------------------------------------------------
__global__ __launch_bounds__(256, 4)
void ctx_softmax(const int* __restrict__ mask, float* __restrict__ out)
{
    __shared__ float ws[N_];
    __shared__ float sred[256];
    const int b = blockIdx.y;
    const int t = threadIdx.x;

    const int mk0 = mask[b * N_ + t];
    const int mk1 = mask[b * N_ + t + 256];
    float l0 = 0.f, l1 = 0.f;
    #pragma unroll
    for (int ct = 0; ct < 8; ct++) {
        l0 += g_part8[ct][b * N_ + t];
        l1 += g_part8[ct][b * N_ + t + 256];
    }

    int any = __syncthreads_or(mk0 | mk1);
    if (!any) {                      // whole row masked -> context = 0
        float2 z = {0.f, 0.f};
        ((float2*)(out + b * D_))[blockIdx.x * 256 + t] = z;
        return;
    }
    float x0 = mk0 ? l0 : -1e30f;
    float x1 = mk1 ? l1 : -1e30f;

    sred[t] = fmaxf(x0, x1);
    __syncthreads();
    #pragma unroll
    for (int st = 128; st > 0; st >>= 1) {
        if (t < st) sred[t] = fmaxf(sred[t], sred[t + st]);
        __syncthreads();
    }
    const float mx = sred[0];
    __syncthreads();
    const float e0 = expf(x0 - mx);   // masked lanes underflow to exactly 0
    const float e1 = expf(x1 - mx);
    sred[t] = e0 + e1;
    __syncthreads();
    #pragma unroll
    for (int st = 128; st > 0; st >>= 1) {
        if (t < st) sred[t] += sred[t + st];
        __syncthreads();
    }
    const float inv = 1.f / sred[0];
    ws[t]       = e0 * inv;
    ws[t + 256] = e1 * inv;
    __syncthreads();

    // context: this thread owns fp32 output cols d, d+1 (swizzled reads)
    const int d      = 2 * (blockIdx.x * 256 + t);
    const int kt     = d >> 6;
    const uint32_t off_d = (uint32_t)(((d & 63) >> 3) * 16 + (d & 7) * 2);

    float2 a0 = {0.f, 0.f}, a1 = {0.f, 0.f}, a2 = {0.f, 0.f}, a3 = {0.f, 0.f};
    #pragma unroll
    for (int nb = 0; nb < 4; nb++) {
        const unsigned char* base = g_MhT + (size_t)((b * 4 + nb) * 16 + kt) * CHB;
        const float* w = ws + nb * 128;
        #pragma unroll 4
        for (int r = 0; r < 128; r += 4) {
            float2 m0 = __half22float2(*(const __half2*)(base + (r + 0) * 128 + (off_d ^ (((r + 0) & 7) << 4))));
            float2 m1 = __half22float2(*(const __half2*)(base + (r + 1) * 128 + (off_d ^ (((r + 1) & 7) << 4))));
            float2 m2 = __half22float2(*(const __half2*)(base + (r + 2) * 128 + (off_d ^ (((r + 2) & 7) << 4))));
            float2 m3 = __half22float2(*(const __half2*)(base + (r + 3) * 128 + (off_d ^ (((r + 3) & 7) << 4))));
            a0.x += w[r + 0] * m0.x; a0.y += w[r + 0] * m0.y;
            a1.x += w[r + 1] * m1.x; a1.y += w[r + 1] * m1.y;
            a2.x += w[r + 2] * m2.x; a2.y += w[r + 2] * m2.y;
            a3.x += w[r + 3] * m3.x; a3.y += w[r + 3] * m3.y;
        }
    }
    float2 rr;
    rr.x = (a0.x + a1.x) + (a2.x + a3.x);
    rr.y = (a0.y + a1.y) + (a2.y + a3.y);
    ((float2*)(out + b * D_))[blockIdx.x * 256 + t] = rr;
}

// ---------------------------------------------------------------------------
extern "C" void kernel_launch(void* const* d_in, const int* in_sizes, int n_in,
                              void* d_out, int out_size)
{
    const float* M     = (const float*)d_in[0];  // (64, 512, 1024)
    const int*   mask  = (const int*)  d_in[1];  // (64, 512)
    const float* query = (const float*)d_in[2];  // (64, 1024)
    const float* Wh    = (const float*)d_in[3];  // (1024, 1024)
    const float* Ws    = (const float*)d_in[4];  // (1024, 1024)
    const float* v     = (const float*)d_in[5];  // (1024, 1)
    float* out = (float*)d_out;                  // (64, 1024)

    cudaFuncSetAttribute(logits_mma, cudaFuncAttributeMaxDynamicSharedMemorySize, SMTOT);

    prep_kernel<<<TQ_BLKS + TRAN_BLKS + CONV_BLKS, 256>>>(M, Wh, query, Ws);
    logits_mma<<<296, 256, SMTOT>>>(v);
    ctx_softmax<<<dim3(2, B_), 256>>>(mask, out);
}